// round 13
// baseline (speedup 1.0000x reference)
#include <cuda_runtime.h>
#include <math.h>

// Problem constants
#define NCHUNK 32
#define NBATCH 64
#define HALF   128
#define SIZE   256
#define NROWS  (NCHUNK * NBATCH)          // 2048
#define C_SCALE 1e-4f
#define M_SCALE 1e-5f

#define M_PER_MAT   (SIZE * SIZE / 4)     // 16384 float4 per matrix
#define STORES_PER_THREAD 8
#define TOTAL_F4    (M_PER_MAT * NROWS)   // 33,554,432 float4
#define JMAT_BLOCKS (TOTAL_F4 / (256 * STORES_PER_THREAD))  // 16384
#define YDOT_BLOCKS (NROWS / 2)           // 1024 (2 rows per block)

// ---------------------------------------------------------------------------
// Fused kernel, J-first ordering (best measured kernel time had ydot last).
// Blocks [0, JMAT_BLOCKS): J writer. 8 warps/CTA; each warp owns a
//   CONTIGUOUS 4KB region (256 float4). Lane l, step s writes
//   base + s*32 + l  -> every STG.128 is a fully-coalesced 512B warp
//   transaction, the warp's 8 transactions tile the 4KB region linearly,
//   and the global stream across CTAs is perfectly sequential.
//   8 back-to-back independent STGs per thread -> deep store MLP;
//   16K CTAs instead of 131K -> less dispatch/tail overhead.
// Blocks [JMAT_BLOCKS, +YDOT_BLOCKS): ydot, 2 rows per 256-thread block.
// ---------------------------------------------------------------------------
__global__ void __launch_bounds__(256) fused_kernel(
    const float* __restrict__ t,
    const float* __restrict__ y,
    const float* __restrict__ K,
    const float* __restrict__ C,
    const float* __restrict__ M,
    float* __restrict__ ydot_out,
    float4* __restrict__ J)
{
    if (blockIdx.x < JMAT_BLOCKS) {
        // ------------------- J stream -------------------
        const unsigned warpGlobal = blockIdx.x * 8u + (threadIdx.x >> 5);
        const unsigned lane = threadIdx.x & 31u;
        const unsigned base = warpGlobal * 256u + lane;   // float4 index

        #pragma unroll
        for (int s = 0; s < STORES_PER_THREAD; s++) {
            const unsigned q = base + (unsigned)s * 32u;
            const unsigned m = q & (M_PER_MAT - 1u);   // position within matrix
            const int r  = (int)(m >> 6);              // row 0..255
            const int c0 = (int)(m & 63u) << 2;        // first of 4 columns

            float4 val = make_float4(0.f, 0.f, 0.f, 0.f);
            float* vv = reinterpret_cast<float*>(&val);

            if (r < HALF) {
                const int tc = r + HALF;               // identity column
                if ((tc & ~3) == c0) vv[tc & 3] = 1.0f;
            } else {
                const int i = r - HALF;
                const int j0 = c0 & (HALF - 1);
                if (j0 <= i + 1 && j0 + 3 >= i - 1) {
                    const bool isv = (c0 >= HALF);
                    const float rM = 1.0f / (M[i] * M_SCALE);
                    const float a  = isv ? (C[i] * C_SCALE) : K[i];
                    const float am = (i > 0) ? (isv ? (C[i - 1] * C_SCALE) : K[i - 1]) : 0.0f;
                    const float diag = -(a + am) * rM;
                    const float sup  = a * rM;
                    const float sub  = am * rM;
                    #pragma unroll
                    for (int kk = 0; kk < 4; kk++) {
                        const int j = j0 + kk;
                        vv[kk] = (j == i) ? diag : (j == i + 1) ? sup : (j == i - 1) ? sub : 0.0f;
                    }
                }
            }
            __stcs(&J[q], val);                        // streaming store
        }
    } else {
        // ------------------- ydot -------------------
        const int sub = threadIdx.x >> 7;              // 0 or 1: which row
        const int i   = threadIdx.x & (HALF - 1);      // 0..127
        const int row = (int)(blockIdx.x - JMAT_BLOCKS) * 2 + sub;

        const float* yr = y + (size_t)row * SIZE;
        float* o = ydot_out + (size_t)row * SIZE;

        __shared__ float su[2][HALF];
        __shared__ float sv[2][HALF];
        __shared__ float sf[2][HALF];

        const float u = yr[i];
        const float v = yr[HALF + i];
        su[sub][i] = u;
        sv[sub][i] = v;
        __syncthreads();

        const float Ki  = K[i];
        const float Csi = C[i] * C_SCALE;
        const float Msi = M[i] * M_SCALE;

        float fi = 0.0f;
        if (i < HALF - 1) {
            fi = Ki * (su[sub][i + 1] - u) + Csi * (sv[sub][i + 1] - v);
        }
        sf[sub][i] = fi;
        __syncthreads();

        float num = fi;                               // f[i] term (0 for i==127)
        if (i > 0) num -= sf[sub][i - 1];             // -f[i-1]
        float vdot = num / Msi;
        if (i == HALF - 1) vdot -= (Ki * u + Csi * v) / Msi;
        if (i == 0)        vdot += sinf(t[row]) / Msi;

        o[i]        = v;
        o[HALF + i] = vdot;
    }
}

// ---------------------------------------------------------------------------
// launch
// ---------------------------------------------------------------------------
extern "C" void kernel_launch(void* const* d_in, const int* in_sizes, int n_in,
                              void* d_out, int out_size)
{
    const float* t = (const float*)d_in[0];   // (32,64)
    const float* y = (const float*)d_in[1];   // (32,64,256)
    const float* K = (const float*)d_in[2];   // (128,)
    const float* C = (const float*)d_in[3];   // (128,)
    const float* M = (const float*)d_in[4];   // (128,)

    float* out = (float*)d_out;
    float* ydot = out;                                   // 2048*256 floats
    float4* J = (float4*)(out + (size_t)NROWS * SIZE);   // 2048*256*256 floats

    fused_kernel<<<JMAT_BLOCKS + YDOT_BLOCKS, 256>>>(t, y, K, C, M, ydot, J);
}